// round 15
// baseline (speedup 1.0000x reference)
#include <cuda_runtime.h>
#include <cuda_fp16.h>
#include <cstdint>
#include <math.h>

// Problem dims (fixed by the dataset)
#define M_TOK 8192   // B*S
#define HID   2048   // hidden
#define INTER 8192   // intermediate

// ---------------- scratch (allocation-free rule: __device__ globals) --------
__device__ __half g_y[(size_t)M_TOK * HID];       // LN output (fp16)              32 MB
__device__ __half g_z[(size_t)M_TOK * INTER];     // GeGLU output (fp16)          128 MB
__device__ __half g_w1t[(size_t)2 * INTER * HID]; // W1^T rows n=2i+a [16384,2048] 64 MB
__device__ __half g_w2t[(size_t)HID * INTER];     // W2^T [2048,8192]              32 MB
__device__ float  g_p[(size_t)2 * M_TOK * HID];   // split-K partials (fp32)      128 MB

// ---------------- helpers ---------------------------------------------------
__device__ __forceinline__ void cp16(uint32_t dst_smem, const void* src) {
    asm volatile("cp.async.cg.shared.global [%0], [%1], 16;\n" ::"r"(dst_smem), "l"(src));
}
__device__ __forceinline__ void cp_commit() { asm volatile("cp.async.commit_group;\n"); }

__device__ __forceinline__ void mma_f16(float* c, const uint32_t* a, const uint32_t* b) {
    asm volatile(
        "mma.sync.aligned.m16n8k16.row.col.f32.f16.f16.f32 "
        "{%0,%1,%2,%3}, {%4,%5,%6,%7}, {%8,%9}, {%0,%1,%2,%3};\n"
        : "+f"(c[0]), "+f"(c[1]), "+f"(c[2]), "+f"(c[3])
        : "r"(a[0]), "r"(a[1]), "r"(a[2]), "r"(a[3]), "r"(b[0]), "r"(b[1]));
}
// ldmatrix of four 8x8 b16 tiles
__device__ __forceinline__ void ldsm4(uint32_t* r, uint32_t addr) {
    asm volatile("ldmatrix.sync.aligned.m8n8.x4.shared.b16 {%0,%1,%2,%3}, [%4];"
                 : "=r"(r[0]), "=r"(r[1]), "=r"(r[2]), "=r"(r[3]) : "r"(addr));
}
__device__ __forceinline__ float gelu_tanh(float h) {
    return 0.5f * h * (1.0f + tanhf(0.7978845608028654f * (h + 0.044715f * h * h * h)));
}
// streaming (evict-first) stores
__device__ __forceinline__ void st16_cs(__half* p, __half v) {
    unsigned short u = __half_as_ushort(v);
    asm volatile("st.global.cs.u16 [%0], %1;" ::"l"(p), "h"(u) : "memory");
}
__device__ __forceinline__ void st64_cs(float* p, float x, float y) {
    asm volatile("st.global.cs.v2.f32 [%0], {%1, %2};" ::"l"(p), "f"(x), "f"(y) : "memory");
}

// ---------------- LayerNorm (fp32 math, fp16 out) ---------------------------
__global__ void ln_kernel(const float* __restrict__ x,
                          const float* __restrict__ scale,
                          const float* __restrict__ bias) {
    const int row = blockIdx.x;
    const float4* xr = reinterpret_cast<const float4*>(x + (size_t)row * HID);
    float4 v[2];
    v[0] = xr[threadIdx.x];
    v[1] = xr[threadIdx.x + 256];

    float s = 0.f, ss = 0.f;
#pragma unroll
    for (int i = 0; i < 2; i++) {
        s += v[i].x + v[i].y + v[i].z + v[i].w;
        ss += v[i].x * v[i].x + v[i].y * v[i].y + v[i].z * v[i].z + v[i].w * v[i].w;
    }
#pragma unroll
    for (int o = 16; o; o >>= 1) {
        s += __shfl_xor_sync(0xFFFFFFFFu, s, o);
        ss += __shfl_xor_sync(0xFFFFFFFFu, ss, o);
    }
    __shared__ float rs[8], rss[8];
    const int w = threadIdx.x >> 5, l = threadIdx.x & 31;
    if (l == 0) { rs[w] = s; rss[w] = ss; }
    __syncthreads();
    if (threadIdx.x == 0) {
        float S = 0.f, SS = 0.f;
#pragma unroll
        for (int i = 0; i < 8; i++) { S += rs[i]; SS += rss[i]; }
        rs[0] = S; rss[0] = SS;
    }
    __syncthreads();
    const float mean = rs[0] * (1.0f / HID);
    const float var  = rss[0] * (1.0f / HID) - mean * mean;
    const float rstd = rsqrtf(var + 1e-6f);

    __half2* yr = reinterpret_cast<__half2*>(g_y + (size_t)row * HID);
    const float4* sc4 = reinterpret_cast<const float4*>(scale);
    const float4* b4  = reinterpret_cast<const float4*>(bias);
#pragma unroll
    for (int i = 0; i < 2; i++) {
        const int c = threadIdx.x + i * 256;
        float4 sv = sc4[c], bv = b4[c], xv = v[i];
        const float ox = (xv.x - mean) * rstd * sv.x + bv.x;
        const float oy = (xv.y - mean) * rstd * sv.y + bv.y;
        const float oz = (xv.z - mean) * rstd * sv.z + bv.z;
        const float ow = (xv.w - mean) * rstd * sv.w + bv.w;
        yr[2 * c]     = __floats2half2_rn(ox, oy);
        yr[2 * c + 1] = __floats2half2_rn(oz, ow);
    }
}

// ---------------- weight transposes (coalesced, fp16 out) --------------------
// W1 [2048, 16384] -> g_w1t rows n=2i+a (branch-interleaved), K contiguous
__global__ void transpose_w1(const float* __restrict__ w1) {
    __shared__ float t[32][33];
    const int j0 = blockIdx.x * 32;  // col in W1 (0..16383)
    const int k0 = blockIdx.y * 32;  // row in W1 (0..2047)
#pragma unroll
    for (int r = threadIdx.y; r < 32; r += 8)
        t[r][threadIdx.x] = w1[(size_t)(k0 + r) * (2 * INTER) + j0 + threadIdx.x];
    __syncthreads();
#pragma unroll
    for (int r = threadIdx.y; r < 32; r += 8) {
        const int j = j0 + r;
        const int a = j >> 13, i = j & (INTER - 1);
        const int n = 2 * i + a;
        g_w1t[(size_t)n * HID + k0 + threadIdx.x] = __float2half_rn(t[threadIdx.x][r]);
    }
}
// W2 [8192, 2048] -> g_w2t [2048, 8192]
__global__ void transpose_w2(const float* __restrict__ w2) {
    __shared__ float t[32][33];
    const int j0 = blockIdx.x * 32;  // col in W2 (0..2047)
    const int k0 = blockIdx.y * 32;  // row in W2 (0..8191)
#pragma unroll
    for (int r = threadIdx.y; r < 32; r += 8)
        t[r][threadIdx.x] = w2[(size_t)(k0 + r) * HID + j0 + threadIdx.x];
    __syncthreads();
#pragma unroll
    for (int r = threadIdx.y; r < 32; r += 8)
        g_w2t[(size_t)(j0 + r) * INTER + k0 + threadIdx.x] = __float2half_rn(t[threadIdx.x][r]);
}

// ---------------- split-K reduction: out = p0 + p1 ---------------------------
__global__ void reduce_out(float* __restrict__ out) {
    const size_t i = ((size_t)blockIdx.x * 256 + threadIdx.x) * 4;
    const float4 a = *reinterpret_cast<const float4*>(&g_p[i]);
    const float4 b = *reinterpret_cast<const float4*>(&g_p[(size_t)M_TOK * HID + i]);
    float4 o = make_float4(a.x + b.x, a.y + b.y, a.z + b.z, a.w + b.w);
    *reinterpret_cast<float4*>(out + i) = o;
}

// ---------------- fp16 mma.sync GEMM (fp32 accum) ----------------------------
// R13 structure (proven): CTA 128x128, BK=32 halfs, 256 threads = 8 warps (2x4),
// warp tile 64x32, 6-stage cp.async (96 KB smem), 2 CTAs/SM, kt unrolled x2
// (one wait_group(2)+syncthreads per 2 stages, fill distance +4/+5).
// NEW: SPLITS template — GEMM2 runs as 2 K-halves (2048 CTAs) into g_p,
// fixing the 3.46-wave tail quantization. Mainloop untouched.
constexpr int CBM = 128, CBN = 128, CBK = 32, STG = 6;
constexpr uint32_t A_BYTES  = CBM * CBK * 2;   // 8192
constexpr uint32_t ST_BYTES = 2 * A_BYTES;     // 16384
constexpr uint32_t GSMEM    = STG * ST_BYTES;  // 98304

template <bool GEGLU, int NT, int SPLITS>
__global__ __launch_bounds__(256, 2) void mm_kernel(float* __restrict__ OutP, int Kstride) {
    extern __shared__ char smem[];
    const uint32_t sbase = (uint32_t)__cvta_generic_to_shared(smem);
    const int tid = threadIdx.x;

    const __half* Ap = GEGLU ? g_y : g_z;
    const __half* Bp = GEGLU ? g_w1t : g_w2t;

    // split-K decode (compile-time no-op for SPLITS==1)
    int bid = blockIdx.x;
    int kOff = 0;
    const int Klen = Kstride / SPLITS;
    if (SPLITS > 1) {
        const int tilesPerSplit = (M_TOK / CBM) * NT;
        const int split = bid / tilesPerSplit;
        bid -= split * tilesPerSplit;
        kOff = split * Klen;
        OutP += (size_t)split * M_TOK * HID;
    }

    // grouped raster: groups of GM m-tiles x NT n-tiles (L2-resident wave)
    const int GM = 16;
    const int tpg = GM * NT;
    const int grp = bid / tpg;
    const int rr  = bid - grp * tpg;
    const int m0 = (grp * GM + (rr % GM)) * CBM;
    const int n0 = (rr / GM) * CBN;

    // ---- loader: 2 threads per row; each loads 2x 16B chunks of A and B ----
    const int lrow = tid >> 1;
    const int lch0 = (tid & 1) * 2;
    const __half* aSrc = Ap + (size_t)(m0 + lrow) * Kstride + kOff + lch0 * 8;
    const __half* bSrc = Bp + (size_t)(n0 + lrow) * Kstride + kOff + lch0 * 8;
    const uint32_t rowSw  = (uint32_t)((lrow >> 1) & 3);
    const uint32_t rowOff = (uint32_t)lrow * 64u;

    auto fill = [&](int kt, int s) {
        const uint32_t base = sbase + (uint32_t)s * ST_BYTES;
        const __half* a = aSrc + (size_t)kt * CBK;
        const __half* b = bSrc + (size_t)kt * CBK;
#pragma unroll
        for (int c = 0; c < 2; c++)
            cp16(base + rowOff + ((((uint32_t)(lch0 + c)) ^ rowSw) << 4), a + c * 8);
#pragma unroll
        for (int c = 0; c < 2; c++)
            cp16(base + A_BYTES + rowOff + ((((uint32_t)(lch0 + c)) ^ rowSw) << 4), b + c * 8);
    };

    // ---- per-lane ldmatrix addresses ----
    const int lane = tid & 31, w = tid >> 5;
    const int wm = w >> 2, wn = w & 3;            // 2x4 warps, 64x32 tiles
    const int a_tile = lane >> 3;
    const int a_r = wm * 64 + (a_tile & 1) * 8 + (lane & 7);
    const int a_cc = a_tile >> 1;
    const int a_s = (a_r >> 1) & 3;
    const int b_n = wn * 32 + (lane & 7) + ((lane >> 4) & 1) * 8;
    const int b_cc = (lane >> 3) & 1;
    const int b_s = (b_n >> 1) & 3;
    uint32_t aoff[2], boff[2];
#pragma unroll
    for (int ks = 0; ks < 2; ks++) {
        aoff[ks] = (uint32_t)(a_r * 64 + (((2 * ks + a_cc) ^ a_s) << 4));
        boff[ks] = A_BYTES + (uint32_t)(b_n * 64 + (((2 * ks + b_cc) ^ b_s) << 4));
    }

    const int kIters = Klen / CBK;
    // prologue: fill stages 0..3 (4 commit groups)
#pragma unroll
    for (int s = 0; s < STG - 2; s++) { fill(s, s); cp_commit(); }

    float acc[4][4][4];
#pragma unroll
    for (int a = 0; a < 4; a++)
#pragma unroll
        for (int b = 0; b < 4; b++)
#pragma unroll
            for (int c = 0; c < 4; c++) acc[a][b][c] = 0.f;

    int scur = 0, sload = STG - 2;   // next stage to fill = 4
    for (int kt = 0; kt < kIters; kt += 2) {
        // publish stages kt and kt+1 (pending groups after wait: 2)
        asm volatile("cp.async.wait_group 2;\n");
        __syncthreads();
#pragma unroll
        for (int h = 0; h < 2; h++) {
            const int nk = kt + 4 + h;           // fill distance +4 / +5
            if (nk < kIters) fill(nk, sload);
            cp_commit();
            if (++sload == STG) sload = 0;

            const uint32_t stb = sbase + (uint32_t)scur * ST_BYTES;
            if (++scur == STG) scur = 0;
#pragma unroll
            for (int ks = 0; ks < 2; ks++) {
                uint32_t af[4][4], bf[4][2];
#pragma unroll
                for (int mt = 0; mt < 4; mt++)
                    ldsm4(af[mt], stb + aoff[ks] + (uint32_t)mt * 1024u);
#pragma unroll
                for (int nq = 0; nq < 2; nq++) {
                    uint32_t t4[4];
                    ldsm4(t4, stb + boff[ks] + (uint32_t)nq * 1024u);
                    bf[2 * nq][0] = t4[0]; bf[2 * nq][1] = t4[1];
                    bf[2 * nq + 1][0] = t4[2]; bf[2 * nq + 1][1] = t4[3];
                }
#pragma unroll
                for (int mt = 0; mt < 4; mt++)
#pragma unroll
                    for (int nt = 0; nt < 4; nt++)
                        mma_f16(acc[mt][nt], af[ks == 0 ? mt : mt], bf[nt]);
            }
        }
    }

    // ---- epilogue (register-resident, streaming stores) ----
    const int g = lane >> 2, t = lane & 3;
    if (GEGLU) {
        const int ibase = (n0 >> 1) + wn * 16;
#pragma unroll
        for (int mt = 0; mt < 4; mt++) {
            const int r = m0 + wm * 64 + mt * 16 + g;
#pragma unroll
            for (int nt = 0; nt < 4; nt++) {
                const int ig = ibase + nt * 4 + t;
                // even col = gelu branch, odd col = linear branch (n = 2i+a)
                st16_cs(&g_z[(size_t)r * INTER + ig],
                        __float2half_rn(gelu_tanh(acc[mt][nt][0]) * acc[mt][nt][1]));
                st16_cs(&g_z[(size_t)(r + 8) * INTER + ig],
                        __float2half_rn(gelu_tanh(acc[mt][nt][2]) * acc[mt][nt][3]));
            }
        }
    } else {
#pragma unroll
        for (int mt = 0; mt < 4; mt++) {
            const int r = m0 + wm * 64 + mt * 16 + g;
#pragma unroll
            for (int nt = 0; nt < 4; nt++) {
                const int c = n0 + wn * 32 + nt * 8 + 2 * t;
                st64_cs(OutP + (size_t)r * HID + c, acc[mt][nt][0], acc[mt][nt][1]);
                st64_cs(OutP + (size_t)(r + 8) * HID + c, acc[mt][nt][2], acc[mt][nt][3]);
            }
        }
    }
}

// ---------------- launch ----------------------------------------------------
extern "C" void kernel_launch(void* const* d_in, const int* in_sizes, int n_in,
                              void* d_out, int out_size) {
    (void)in_sizes; (void)n_in; (void)out_size;
    const float* x     = (const float*)d_in[0];
    const float* scale = (const float*)d_in[1];
    const float* bias  = (const float*)d_in[2];
    const float* w1    = (const float*)d_in[3];  // [H, 2, I] row-major == [H, 2*I]
    const float* w2    = (const float*)d_in[4];  // [I, H]
    float* out = (float*)d_out;

    float* p_base;
    cudaGetSymbolAddress((void**)&p_base, g_p);

    cudaFuncSetAttribute(mm_kernel<true, 128, 1>,
                         cudaFuncAttributeMaxDynamicSharedMemorySize, (int)GSMEM);
    cudaFuncSetAttribute(mm_kernel<false, 16, 2>,
                         cudaFuncAttributeMaxDynamicSharedMemorySize, (int)GSMEM);

    transpose_w1<<<dim3((2 * INTER) / 32, HID / 32), dim3(32, 8)>>>(w1);
    transpose_w2<<<dim3(HID / 32, INTER / 32), dim3(32, 8)>>>(w2);
    ln_kernel<<<M_TOK, 256>>>(x, scale, bias);

    // GEMM1 + fused GeGLU: [8192 x 2048] @ W1t^T -> g_z   (64 x 128 tiles)
    mm_kernel<true, 128, 1><<<(M_TOK / CBM) * (2 * INTER / CBN), 256, GSMEM>>>(nullptr, HID);
    // GEMM2 split-K=2: [8192 x 8192] @ W2t^T -> g_p       (64 x 16 x 2 tiles)
    mm_kernel<false, 16, 2><<<(M_TOK / CBM) * (HID / CBN) * 2, 256, GSMEM>>>(p_base, INTER);
    // out = p0 + p1
    reduce_out<<<(M_TOK * HID) / (256 * 4), 256>>>(out);
}

// round 16
// speedup vs baseline: 1.0723x; 1.0723x over previous
#include <cuda_runtime.h>
#include <cuda_fp16.h>
#include <cstdint>
#include <math.h>

// Problem dims (fixed by the dataset)
#define M_TOK 8192   // B*S
#define HID   2048   // hidden
#define INTER 8192   // intermediate

// ---------------- scratch (allocation-free rule: __device__ globals) --------
__device__ __half g_y[(size_t)M_TOK * HID];       // LN output (fp16)              32 MB
__device__ __half g_z[(size_t)M_TOK * INTER];     // GeGLU output (fp16)          128 MB
__device__ __half g_w1t[(size_t)2 * INTER * HID]; // W1^T rows n=2i+a [16384,2048] 64 MB
__device__ __half g_w2t[(size_t)HID * INTER];     // W2^T [2048,8192]              32 MB

// ---------------- helpers ---------------------------------------------------
__device__ __forceinline__ void cp16(uint32_t dst_smem, const void* src) {
    asm volatile("cp.async.cg.shared.global [%0], [%1], 16;\n" ::"r"(dst_smem), "l"(src));
}
__device__ __forceinline__ void cp_commit() { asm volatile("cp.async.commit_group;\n"); }

__device__ __forceinline__ void mma_f16(float* c, const uint32_t* a, const uint32_t* b) {
    asm volatile(
        "mma.sync.aligned.m16n8k16.row.col.f32.f16.f16.f32 "
        "{%0,%1,%2,%3}, {%4,%5,%6,%7}, {%8,%9}, {%0,%1,%2,%3};\n"
        : "+f"(c[0]), "+f"(c[1]), "+f"(c[2]), "+f"(c[3])
        : "r"(a[0]), "r"(a[1]), "r"(a[2]), "r"(a[3]), "r"(b[0]), "r"(b[1]));
}
// ldmatrix of four 8x8 b16 tiles
__device__ __forceinline__ void ldsm4(uint32_t* r, uint32_t addr) {
    asm volatile("ldmatrix.sync.aligned.m8n8.x4.shared.b16 {%0,%1,%2,%3}, [%4];"
                 : "=r"(r[0]), "=r"(r[1]), "=r"(r[2]), "=r"(r[3]) : "r"(addr));
}
__device__ __forceinline__ float gelu_tanh(float h) {
    return 0.5f * h * (1.0f + tanhf(0.7978845608028654f * (h + 0.044715f * h * h * h)));
}
// streaming (evict-first) stores
__device__ __forceinline__ void st16_cs(__half* p, __half v) {
    unsigned short u = __half_as_ushort(v);
    asm volatile("st.global.cs.u16 [%0], %1;" ::"l"(p), "h"(u) : "memory");
}
__device__ __forceinline__ void st64_cs(float* p, float x, float y) {
    asm volatile("st.global.cs.v2.f32 [%0], {%1, %2};" ::"l"(p), "f"(x), "f"(y) : "memory");
}

// ---------------- LayerNorm (fp32 math, fp16 out) ---------------------------
__global__ void ln_kernel(const float* __restrict__ x,
                          const float* __restrict__ scale,
                          const float* __restrict__ bias) {
    const int row = blockIdx.x;
    const float4* xr = reinterpret_cast<const float4*>(x + (size_t)row * HID);
    float4 v[2];
    v[0] = xr[threadIdx.x];
    v[1] = xr[threadIdx.x + 256];

    float s = 0.f, ss = 0.f;
#pragma unroll
    for (int i = 0; i < 2; i++) {
        s += v[i].x + v[i].y + v[i].z + v[i].w;
        ss += v[i].x * v[i].x + v[i].y * v[i].y + v[i].z * v[i].z + v[i].w * v[i].w;
    }
#pragma unroll
    for (int o = 16; o; o >>= 1) {
        s += __shfl_xor_sync(0xFFFFFFFFu, s, o);
        ss += __shfl_xor_sync(0xFFFFFFFFu, ss, o);
    }
    __shared__ float rs[8], rss[8];
    const int w = threadIdx.x >> 5, l = threadIdx.x & 31;
    if (l == 0) { rs[w] = s; rss[w] = ss; }
    __syncthreads();
    if (threadIdx.x == 0) {
        float S = 0.f, SS = 0.f;
#pragma unroll
        for (int i = 0; i < 8; i++) { S += rs[i]; SS += rss[i]; }
        rs[0] = S; rss[0] = SS;
    }
    __syncthreads();
    const float mean = rs[0] * (1.0f / HID);
    const float var  = rss[0] * (1.0f / HID) - mean * mean;
    const float rstd = rsqrtf(var + 1e-6f);

    __half2* yr = reinterpret_cast<__half2*>(g_y + (size_t)row * HID);
    const float4* sc4 = reinterpret_cast<const float4*>(scale);
    const float4* b4  = reinterpret_cast<const float4*>(bias);
#pragma unroll
    for (int i = 0; i < 2; i++) {
        const int c = threadIdx.x + i * 256;
        float4 sv = sc4[c], bv = b4[c], xv = v[i];
        const float ox = (xv.x - mean) * rstd * sv.x + bv.x;
        const float oy = (xv.y - mean) * rstd * sv.y + bv.y;
        const float oz = (xv.z - mean) * rstd * sv.z + bv.z;
        const float ow = (xv.w - mean) * rstd * sv.w + bv.w;
        yr[2 * c]     = __floats2half2_rn(ox, oy);
        yr[2 * c + 1] = __floats2half2_rn(oz, ow);
    }
}

// ---------------- weight transposes (coalesced, fp16 out) --------------------
// W1 [2048, 16384] -> g_w1t rows n=2i+a (branch-interleaved), K contiguous
__global__ void transpose_w1(const float* __restrict__ w1) {
    __shared__ float t[32][33];
    const int j0 = blockIdx.x * 32;  // col in W1 (0..16383)
    const int k0 = blockIdx.y * 32;  // row in W1 (0..2047)
#pragma unroll
    for (int r = threadIdx.y; r < 32; r += 8)
        t[r][threadIdx.x] = w1[(size_t)(k0 + r) * (2 * INTER) + j0 + threadIdx.x];
    __syncthreads();
#pragma unroll
    for (int r = threadIdx.y; r < 32; r += 8) {
        const int j = j0 + r;
        const int a = j >> 13, i = j & (INTER - 1);
        const int n = 2 * i + a;
        g_w1t[(size_t)n * HID + k0 + threadIdx.x] = __float2half_rn(t[threadIdx.x][r]);
    }
}
// W2 [8192, 2048] -> g_w2t [2048, 8192]
__global__ void transpose_w2(const float* __restrict__ w2) {
    __shared__ float t[32][33];
    const int j0 = blockIdx.x * 32;  // col in W2 (0..2047)
    const int k0 = blockIdx.y * 32;  // row in W2 (0..8191)
#pragma unroll
    for (int r = threadIdx.y; r < 32; r += 8)
        t[r][threadIdx.x] = w2[(size_t)(k0 + r) * HID + j0 + threadIdx.x];
    __syncthreads();
#pragma unroll
    for (int r = threadIdx.y; r < 32; r += 8)
        g_w2t[(size_t)(j0 + r) * INTER + k0 + threadIdx.x] = __float2half_rn(t[threadIdx.x][r]);
}

// ---------------- fp16 mma.sync GEMM (fp32 accum) ----------------------------
// R13 structure (proven 2385us): CTA 128x128, BK=32 halfs, 256 threads = 8 warps
// (2x4), warp tile 64x32, 6-stage cp.async (96 KB smem), 2 CTAs/SM, kt unrolled
// x2 (one wait_group(2)+syncthreads per 2 stages, fill distance +4/+5).
// ONE change vs R13: the per-half fill is issued BETWEEN ks=0's MMA block and
// ks=1's LDSM, keeping cp.async issue off the barrier-edge LDSM burst.
// Smem rows = 64B (32 halfs), XOR chunk swizzle: phys-chunk(r,c) = c ^ ((r>>1)&3)
constexpr int CBM = 128, CBN = 128, CBK = 32, STG = 6;
constexpr uint32_t A_BYTES  = CBM * CBK * 2;   // 8192
constexpr uint32_t ST_BYTES = 2 * A_BYTES;     // 16384
constexpr uint32_t GSMEM    = STG * ST_BYTES;  // 98304

template <bool GEGLU, int NT>
__global__ __launch_bounds__(256, 2) void mm_kernel(float* __restrict__ OutP, int Kdim) {
    extern __shared__ char smem[];
    const uint32_t sbase = (uint32_t)__cvta_generic_to_shared(smem);
    const int tid = threadIdx.x;

    const __half* Ap = GEGLU ? g_y : g_z;
    const __half* Bp = GEGLU ? g_w1t : g_w2t;

    // grouped raster: groups of GM m-tiles x NT n-tiles (L2-resident wave)
    const int GM = 16;
    const int tpg = GM * NT;
    const int grp = blockIdx.x / tpg;
    const int rr  = blockIdx.x - grp * tpg;
    const int m0 = (grp * GM + (rr % GM)) * CBM;
    const int n0 = (rr / GM) * CBN;

    // ---- loader: 2 threads per row; each loads 2x 16B chunks of A and B ----
    const int lrow = tid >> 1;
    const int lch0 = (tid & 1) * 2;
    const __half* aSrc = Ap + (size_t)(m0 + lrow) * Kdim + lch0 * 8;
    const __half* bSrc = Bp + (size_t)(n0 + lrow) * Kdim + lch0 * 8;
    const uint32_t rowSw  = (uint32_t)((lrow >> 1) & 3);
    const uint32_t rowOff = (uint32_t)lrow * 64u;

    auto fill = [&](int kt, int s) {
        const uint32_t base = sbase + (uint32_t)s * ST_BYTES;
        const __half* a = aSrc + (size_t)kt * CBK;
        const __half* b = bSrc + (size_t)kt * CBK;
#pragma unroll
        for (int c = 0; c < 2; c++)
            cp16(base + rowOff + ((((uint32_t)(lch0 + c)) ^ rowSw) << 4), a + c * 8);
#pragma unroll
        for (int c = 0; c < 2; c++)
            cp16(base + A_BYTES + rowOff + ((((uint32_t)(lch0 + c)) ^ rowSw) << 4), b + c * 8);
    };

    // ---- per-lane ldmatrix addresses ----
    // chunk cc within a row = 16B = 8 halfs; ks selects k-16 block -> chunks 2ks, 2ks+1
    const int lane = tid & 31, w = tid >> 5;
    const int wm = w >> 2, wn = w & 3;            // 2x4 warps, 64x32 tiles
    const int a_tile = lane >> 3;
    const int a_r = wm * 64 + (a_tile & 1) * 8 + (lane & 7);
    const int a_cc = a_tile >> 1;
    const int a_s = (a_r >> 1) & 3;
    const int b_n = wn * 32 + (lane & 7) + ((lane >> 4) & 1) * 8;
    const int b_cc = (lane >> 3) & 1;
    const int b_s = (b_n >> 1) & 3;
    uint32_t aoff[2], boff[2];
#pragma unroll
    for (int ks = 0; ks < 2; ks++) {
        aoff[ks] = (uint32_t)(a_r * 64 + (((2 * ks + a_cc) ^ a_s) << 4));
        boff[ks] = A_BYTES + (uint32_t)(b_n * 64 + (((2 * ks + b_cc) ^ b_s) << 4));
    }

    const int kIters = Kdim / CBK;
    // prologue: fill stages 0..3 (4 commit groups)
#pragma unroll
    for (int s = 0; s < STG - 2; s++) { fill(s, s); cp_commit(); }

    float acc[4][4][4];
#pragma unroll
    for (int a = 0; a < 4; a++)
#pragma unroll
        for (int b = 0; b < 4; b++)
#pragma unroll
            for (int c = 0; c < 4; c++) acc[a][b][c] = 0.f;

    int scur = 0, sload = STG - 2;   // next stage to fill = 4
    for (int kt = 0; kt < kIters; kt += 2) {
        // publish stages kt and kt+1 (pending groups after wait: 2)
        asm volatile("cp.async.wait_group 2;\n");
        __syncthreads();
#pragma unroll
        for (int h = 0; h < 2; h++) {
            const uint32_t stb = sbase + (uint32_t)scur * ST_BYTES;
            if (++scur == STG) scur = 0;

            // ---- ks = 0: LDSM + MMA ----
            uint32_t af[4][4], bf[4][2];
#pragma unroll
            for (int mt = 0; mt < 4; mt++)
                ldsm4(af[mt], stb + aoff[0] + (uint32_t)mt * 1024u);
#pragma unroll
            for (int nq = 0; nq < 2; nq++) {
                uint32_t t4[4];
                ldsm4(t4, stb + boff[0] + (uint32_t)nq * 1024u);
                bf[2 * nq][0] = t4[0]; bf[2 * nq][1] = t4[1];
                bf[2 * nq + 1][0] = t4[2]; bf[2 * nq + 1][1] = t4[3];
            }
#pragma unroll
            for (int mt = 0; mt < 4; mt++)
#pragma unroll
                for (int nt = 0; nt < 4; nt++)
                    mma_f16(acc[mt][nt], af[mt], bf[nt]);

            // ---- fill next stage while ks=0 MMAs drain ----
            const int nk = kt + 4 + h;           // fill distance +4 / +5
            if (nk < kIters) fill(nk, sload);
            cp_commit();
            if (++sload == STG) sload = 0;

            // ---- ks = 1: LDSM + MMA ----
#pragma unroll
            for (int mt = 0; mt < 4; mt++)
                ldsm4(af[mt], stb + aoff[1] + (uint32_t)mt * 1024u);
#pragma unroll
            for (int nq = 0; nq < 2; nq++) {
                uint32_t t4[4];
                ldsm4(t4, stb + boff[1] + (uint32_t)nq * 1024u);
                bf[2 * nq][0] = t4[0]; bf[2 * nq][1] = t4[1];
                bf[2 * nq + 1][0] = t4[2]; bf[2 * nq + 1][1] = t4[3];
            }
#pragma unroll
            for (int mt = 0; mt < 4; mt++)
#pragma unroll
                for (int nt = 0; nt < 4; nt++)
                    mma_f16(acc[mt][nt], af[mt], bf[nt]);
        }
    }

    // ---- epilogue (register-resident, streaming stores) ----
    const int g = lane >> 2, t = lane & 3;
    if (GEGLU) {
        const int ibase = (n0 >> 1) + wn * 16;
#pragma unroll
        for (int mt = 0; mt < 4; mt++) {
            const int r = m0 + wm * 64 + mt * 16 + g;
#pragma unroll
            for (int nt = 0; nt < 4; nt++) {
                const int ig = ibase + nt * 4 + t;
                // even col = gelu branch, odd col = linear branch (n = 2i+a)
                st16_cs(&g_z[(size_t)r * INTER + ig],
                        __float2half_rn(gelu_tanh(acc[mt][nt][0]) * acc[mt][nt][1]));
                st16_cs(&g_z[(size_t)(r + 8) * INTER + ig],
                        __float2half_rn(gelu_tanh(acc[mt][nt][2]) * acc[mt][nt][3]));
            }
        }
    } else {
#pragma unroll
        for (int mt = 0; mt < 4; mt++) {
            const int r = m0 + wm * 64 + mt * 16 + g;
#pragma unroll
            for (int nt = 0; nt < 4; nt++) {
                const int c = n0 + wn * 32 + nt * 8 + 2 * t;
                st64_cs(OutP + (size_t)r * HID + c, acc[mt][nt][0], acc[mt][nt][1]);
                st64_cs(OutP + (size_t)(r + 8) * HID + c, acc[mt][nt][2], acc[mt][nt][3]);
            }
        }
    }
}

// ---------------- launch ----------------------------------------------------
extern "C" void kernel_launch(void* const* d_in, const int* in_sizes, int n_in,
                              void* d_out, int out_size) {
    (void)in_sizes; (void)n_in; (void)out_size;
    const float* x     = (const float*)d_in[0];
    const float* scale = (const float*)d_in[1];
    const float* bias  = (const float*)d_in[2];
    const float* w1    = (const float*)d_in[3];  // [H, 2, I] row-major == [H, 2*I]
    const float* w2    = (const float*)d_in[4];  // [I, H]
    float* out = (float*)d_out;

    cudaFuncSetAttribute(mm_kernel<true, 128>, cudaFuncAttributeMaxDynamicSharedMemorySize, (int)GSMEM);
    cudaFuncSetAttribute(mm_kernel<false, 16>, cudaFuncAttributeMaxDynamicSharedMemorySize, (int)GSMEM);

    transpose_w1<<<dim3((2 * INTER) / 32, HID / 32), dim3(32, 8)>>>(w1);
    transpose_w2<<<dim3(HID / 32, INTER / 32), dim3(32, 8)>>>(w2);
    ln_kernel<<<M_TOK, 256>>>(x, scale, bias);

    // GEMM1 + fused GeGLU: [8192 x 2048] @ W1t^T -> g_z   (64 x 128 tiles)
    mm_kernel<true, 128><<<(M_TOK / CBM) * (2 * INTER / CBN), 256, GSMEM>>>(nullptr, HID);
    // GEMM2: [8192 x 8192] @ W2t^T -> out                  (64 x 16 tiles)
    mm_kernel<false, 16><<<(M_TOK / CBM) * (HID / CBN), 256, GSMEM>>>(out, INTER);
}

// round 17
// speedup vs baseline: 1.2013x; 1.1203x over previous
#include <cuda_runtime.h>
#include <cuda_fp16.h>
#include <cstdint>
#include <math.h>

// Problem dims (fixed by the dataset)
#define M_TOK 8192   // B*S
#define HID   2048   // hidden
#define INTER 8192   // intermediate

// ---------------- scratch (allocation-free rule: __device__ globals) --------
__device__ __half g_y[(size_t)M_TOK * HID];       // LN output (fp16)              32 MB
__device__ __half g_z[(size_t)M_TOK * INTER];     // GeGLU output (fp16)          128 MB
__device__ __half g_w1t[(size_t)2 * INTER * HID]; // W1^T rows n=2i+a [16384,2048] 64 MB
__device__ __half g_w2t[(size_t)HID * INTER];     // W2^T [2048,8192]              32 MB

// ---------------- helpers ---------------------------------------------------
__device__ __forceinline__ void cp16(uint32_t dst_smem, const void* src) {
    asm volatile("cp.async.cg.shared.global [%0], [%1], 16;\n" ::"r"(dst_smem), "l"(src));
}
__device__ __forceinline__ void cp_commit() { asm volatile("cp.async.commit_group;\n"); }

__device__ __forceinline__ void mma_f16(float* c, const uint32_t* a, const uint32_t* b) {
    asm volatile(
        "mma.sync.aligned.m16n8k16.row.col.f32.f16.f16.f32 "
        "{%0,%1,%2,%3}, {%4,%5,%6,%7}, {%8,%9}, {%0,%1,%2,%3};\n"
        : "+f"(c[0]), "+f"(c[1]), "+f"(c[2]), "+f"(c[3])
        : "r"(a[0]), "r"(a[1]), "r"(a[2]), "r"(a[3]), "r"(b[0]), "r"(b[1]));
}
// ldmatrix of four 8x8 b16 tiles
__device__ __forceinline__ void ldsm4(uint32_t* r, uint32_t addr) {
    asm volatile("ldmatrix.sync.aligned.m8n8.x4.shared.b16 {%0,%1,%2,%3}, [%4];"
                 : "=r"(r[0]), "=r"(r[1]), "=r"(r[2]), "=r"(r[3]) : "r"(addr));
}
__device__ __forceinline__ float gelu_tanh(float h) {
    return 0.5f * h * (1.0f + tanhf(0.7978845608028654f * (h + 0.044715f * h * h * h)));
}
// streaming (evict-first) stores
__device__ __forceinline__ void st16_cs(__half* p, __half v) {
    unsigned short u = __half_as_ushort(v);
    asm volatile("st.global.cs.u16 [%0], %1;" ::"l"(p), "h"(u) : "memory");
}
__device__ __forceinline__ void st64_cs(float* p, float x, float y) {
    asm volatile("st.global.cs.v2.f32 [%0], {%1, %2};" ::"l"(p), "f"(x), "f"(y) : "memory");
}

// ---------------- LayerNorm (fp32 math, fp16 out) ---------------------------
__global__ void ln_kernel(const float* __restrict__ x,
                          const float* __restrict__ scale,
                          const float* __restrict__ bias) {
    const int row = blockIdx.x;
    const float4* xr = reinterpret_cast<const float4*>(x + (size_t)row * HID);
    float4 v[2];
    v[0] = xr[threadIdx.x];
    v[1] = xr[threadIdx.x + 256];

    float s = 0.f, ss = 0.f;
#pragma unroll
    for (int i = 0; i < 2; i++) {
        s += v[i].x + v[i].y + v[i].z + v[i].w;
        ss += v[i].x * v[i].x + v[i].y * v[i].y + v[i].z * v[i].z + v[i].w * v[i].w;
    }
#pragma unroll
    for (int o = 16; o; o >>= 1) {
        s += __shfl_xor_sync(0xFFFFFFFFu, s, o);
        ss += __shfl_xor_sync(0xFFFFFFFFu, ss, o);
    }
    __shared__ float rs[8], rss[8];
    const int w = threadIdx.x >> 5, l = threadIdx.x & 31;
    if (l == 0) { rs[w] = s; rss[w] = ss; }
    __syncthreads();
    if (threadIdx.x == 0) {
        float S = 0.f, SS = 0.f;
#pragma unroll
        for (int i = 0; i < 8; i++) { S += rs[i]; SS += rss[i]; }
        rs[0] = S; rss[0] = SS;
    }
    __syncthreads();
    const float mean = rs[0] * (1.0f / HID);
    const float var  = rss[0] * (1.0f / HID) - mean * mean;
    const float rstd = rsqrtf(var + 1e-6f);

    __half2* yr = reinterpret_cast<__half2*>(g_y + (size_t)row * HID);
    const float4* sc4 = reinterpret_cast<const float4*>(scale);
    const float4* b4  = reinterpret_cast<const float4*>(bias);
#pragma unroll
    for (int i = 0; i < 2; i++) {
        const int c = threadIdx.x + i * 256;
        float4 sv = sc4[c], bv = b4[c], xv = v[i];
        const float ox = (xv.x - mean) * rstd * sv.x + bv.x;
        const float oy = (xv.y - mean) * rstd * sv.y + bv.y;
        const float oz = (xv.z - mean) * rstd * sv.z + bv.z;
        const float ow = (xv.w - mean) * rstd * sv.w + bv.w;
        yr[2 * c]     = __floats2half2_rn(ox, oy);
        yr[2 * c + 1] = __floats2half2_rn(oz, ow);
    }
}

// ---------------- weight transposes (coalesced, fp16 out) --------------------
// W1 [2048, 16384] -> g_w1t rows n=2i+a (branch-interleaved), K contiguous
__global__ void transpose_w1(const float* __restrict__ w1) {
    __shared__ float t[32][33];
    const int j0 = blockIdx.x * 32;  // col in W1 (0..16383)
    const int k0 = blockIdx.y * 32;  // row in W1 (0..2047)
#pragma unroll
    for (int r = threadIdx.y; r < 32; r += 8)
        t[r][threadIdx.x] = w1[(size_t)(k0 + r) * (2 * INTER) + j0 + threadIdx.x];
    __syncthreads();
#pragma unroll
    for (int r = threadIdx.y; r < 32; r += 8) {
        const int j = j0 + r;
        const int a = j >> 13, i = j & (INTER - 1);
        const int n = 2 * i + a;
        g_w1t[(size_t)n * HID + k0 + threadIdx.x] = __float2half_rn(t[threadIdx.x][r]);
    }
}
// W2 [8192, 2048] -> g_w2t [2048, 8192]
__global__ void transpose_w2(const float* __restrict__ w2) {
    __shared__ float t[32][33];
    const int j0 = blockIdx.x * 32;  // col in W2 (0..2047)
    const int k0 = blockIdx.y * 32;  // row in W2 (0..8191)
#pragma unroll
    for (int r = threadIdx.y; r < 32; r += 8)
        t[r][threadIdx.x] = w2[(size_t)(k0 + r) * HID + j0 + threadIdx.x];
    __syncthreads();
#pragma unroll
    for (int r = threadIdx.y; r < 32; r += 8)
        g_w2t[(size_t)(j0 + r) * INTER + k0 + threadIdx.x] = __float2half_rn(t[threadIdx.x][r]);
}

// ---------------- fp16 mma.sync GEMM (fp32 accum) ----------------------------
// R15 structure (proven 2248us): CTA 128x128, BK=32 halfs, 256 threads = 8 warps
// (2x4), warp tile 64x32, 6-stage cp.async (96 KB smem), 2 CTAs/SM, kt unrolled
// x2 (one wait_group(2)+syncthreads per 2 stages, fill distance +4/+5, fill
// issued mid-body).
// Two refinements vs R15:
//  (a) ks0 LDSM issue order interleaved (a0, b-pair0, a1, a2, b-pair1, a3) so
//      the first MMA's operands are ready one LDSM-latency earlier;
//  (b) fill split: A-chunks after ks0 MMA, B-chunks after ks1 LDSM, one commit.
// Smem rows = 64B (32 halfs), XOR chunk swizzle: phys-chunk(r,c) = c ^ ((r>>1)&3)
constexpr int CBM = 128, CBN = 128, CBK = 32, STG = 6;
constexpr uint32_t A_BYTES  = CBM * CBK * 2;   // 8192
constexpr uint32_t ST_BYTES = 2 * A_BYTES;     // 16384
constexpr uint32_t GSMEM    = STG * ST_BYTES;  // 98304

template <bool GEGLU, int NT>
__global__ __launch_bounds__(256, 2) void mm_kernel(float* __restrict__ OutP, int Kdim) {
    extern __shared__ char smem[];
    const uint32_t sbase = (uint32_t)__cvta_generic_to_shared(smem);
    const int tid = threadIdx.x;

    const __half* Ap = GEGLU ? g_y : g_z;
    const __half* Bp = GEGLU ? g_w1t : g_w2t;

    // grouped raster: groups of GM m-tiles x NT n-tiles (L2-resident wave)
    const int GM = 16;
    const int tpg = GM * NT;
    const int grp = blockIdx.x / tpg;
    const int rr  = blockIdx.x - grp * tpg;
    const int m0 = (grp * GM + (rr % GM)) * CBM;
    const int n0 = (rr / GM) * CBN;

    // ---- loader: 2 threads per row; each loads 2x 16B chunks of A and B ----
    const int lrow = tid >> 1;
    const int lch0 = (tid & 1) * 2;
    const __half* aSrc = Ap + (size_t)(m0 + lrow) * Kdim + lch0 * 8;
    const __half* bSrc = Bp + (size_t)(n0 + lrow) * Kdim + lch0 * 8;
    const uint32_t rowSw  = (uint32_t)((lrow >> 1) & 3);
    const uint32_t rowOff = (uint32_t)lrow * 64u;

    auto fillA = [&](int kt, int s) {
        const uint32_t base = sbase + (uint32_t)s * ST_BYTES;
        const __half* a = aSrc + (size_t)kt * CBK;
#pragma unroll
        for (int c = 0; c < 2; c++)
            cp16(base + rowOff + ((((uint32_t)(lch0 + c)) ^ rowSw) << 4), a + c * 8);
    };
    auto fillB = [&](int kt, int s) {
        const uint32_t base = sbase + (uint32_t)s * ST_BYTES;
        const __half* b = bSrc + (size_t)kt * CBK;
#pragma unroll
        for (int c = 0; c < 2; c++)
            cp16(base + A_BYTES + rowOff + ((((uint32_t)(lch0 + c)) ^ rowSw) << 4), b + c * 8);
    };

    // ---- per-lane ldmatrix addresses ----
    // chunk cc within a row = 16B = 8 halfs; ks selects k-16 block -> chunks 2ks, 2ks+1
    const int lane = tid & 31, w = tid >> 5;
    const int wm = w >> 2, wn = w & 3;            // 2x4 warps, 64x32 tiles
    const int a_tile = lane >> 3;
    const int a_r = wm * 64 + (a_tile & 1) * 8 + (lane & 7);
    const int a_cc = a_tile >> 1;
    const int a_s = (a_r >> 1) & 3;
    const int b_n = wn * 32 + (lane & 7) + ((lane >> 4) & 1) * 8;
    const int b_cc = (lane >> 3) & 1;
    const int b_s = (b_n >> 1) & 3;
    uint32_t aoff[2], boff[2];
#pragma unroll
    for (int ks = 0; ks < 2; ks++) {
        aoff[ks] = (uint32_t)(a_r * 64 + (((2 * ks + a_cc) ^ a_s) << 4));
        boff[ks] = A_BYTES + (uint32_t)(b_n * 64 + (((2 * ks + b_cc) ^ b_s) << 4));
    }

    const int kIters = Kdim / CBK;
    // prologue: fill stages 0..3 (4 commit groups)
#pragma unroll
    for (int s = 0; s < STG - 2; s++) { fillA(s, s); fillB(s, s); cp_commit(); }

    float acc[4][4][4];
#pragma unroll
    for (int a = 0; a < 4; a++)
#pragma unroll
        for (int b = 0; b < 4; b++)
#pragma unroll
            for (int c = 0; c < 4; c++) acc[a][b][c] = 0.f;

    int scur = 0, sload = STG - 2;   // next stage to fill = 4
    for (int kt = 0; kt < kIters; kt += 2) {
        // publish stages kt and kt+1 (pending groups after wait: 2)
        asm volatile("cp.async.wait_group 2;\n");
        __syncthreads();
#pragma unroll
        for (int h = 0; h < 2; h++) {
            const uint32_t stb = sbase + (uint32_t)scur * ST_BYTES;
            if (++scur == STG) scur = 0;
            const int nk = kt + 4 + h;           // fill distance +4 / +5

            // ---- ks = 0: LDSM (interleaved: first-MMA operands earliest) ----
            uint32_t af[4][4], bf[4][2];
            {
                uint32_t t4[4];
                ldsm4(af[0], stb + aoff[0]);
                ldsm4(t4, stb + boff[0]);
                bf[0][0] = t4[0]; bf[0][1] = t4[1];
                bf[1][0] = t4[2]; bf[1][1] = t4[3];
                ldsm4(af[1], stb + aoff[0] + 1024u);
                ldsm4(af[2], stb + aoff[0] + 2048u);
                ldsm4(t4, stb + boff[0] + 1024u);
                bf[2][0] = t4[0]; bf[2][1] = t4[1];
                bf[3][0] = t4[2]; bf[3][1] = t4[3];
                ldsm4(af[3], stb + aoff[0] + 3072u);
            }
#pragma unroll
            for (int mt = 0; mt < 4; mt++)
#pragma unroll
                for (int nt = 0; nt < 4; nt++)
                    mma_f16(acc[mt][nt], af[mt], bf[nt]);

            // ---- A-fill in ks0 MMA shadow ----
            if (nk < kIters) fillA(nk, sload);

            // ---- ks = 1: LDSM ----
            {
                uint32_t t4[4];
                ldsm4(af[0], stb + aoff[1]);
                ldsm4(t4, stb + boff[1]);
                bf[0][0] = t4[0]; bf[0][1] = t4[1];
                bf[1][0] = t4[2]; bf[1][1] = t4[3];
                ldsm4(af[1], stb + aoff[1] + 1024u);
                ldsm4(af[2], stb + aoff[1] + 2048u);
                ldsm4(t4, stb + boff[1] + 1024u);
                bf[2][0] = t4[0]; bf[2][1] = t4[1];
                bf[3][0] = t4[2]; bf[3][1] = t4[3];
                ldsm4(af[3], stb + aoff[1] + 3072u);
            }

            // ---- B-fill + commit (one group per half, as before) ----
            if (nk < kIters) fillB(nk, sload);
            cp_commit();
            if (++sload == STG) sload = 0;

#pragma unroll
            for (int mt = 0; mt < 4; mt++)
#pragma unroll
                for (int nt = 0; nt < 4; nt++)
                    mma_f16(acc[mt][nt], af[mt], bf[nt]);
        }
    }

    // ---- epilogue (register-resident, streaming stores) ----
    const int g = lane >> 2, t = lane & 3;
    if (GEGLU) {
        const int ibase = (n0 >> 1) + wn * 16;
#pragma unroll
        for (int mt = 0; mt < 4; mt++) {
            const int r = m0 + wm * 64 + mt * 16 + g;
#pragma unroll
            for (int nt = 0; nt < 4; nt++) {
                const int ig = ibase + nt * 4 + t;
                // even col = gelu branch, odd col = linear branch (n = 2i+a)
                st16_cs(&g_z[(size_t)r * INTER + ig],
                        __float2half_rn(gelu_tanh(acc[mt][nt][0]) * acc[mt][nt][1]));
                st16_cs(&g_z[(size_t)(r + 8) * INTER + ig],
                        __float2half_rn(gelu_tanh(acc[mt][nt][2]) * acc[mt][nt][3]));
            }
        }
    } else {
#pragma unroll
        for (int mt = 0; mt < 4; mt++) {
            const int r = m0 + wm * 64 + mt * 16 + g;
#pragma unroll
            for (int nt = 0; nt < 4; nt++) {
                const int c = n0 + wn * 32 + nt * 8 + 2 * t;
                st64_cs(OutP + (size_t)r * HID + c, acc[mt][nt][0], acc[mt][nt][1]);
                st64_cs(OutP + (size_t)(r + 8) * HID + c, acc[mt][nt][2], acc[mt][nt][3]);
            }
        }
    }
}

// ---------------- launch ----------------------------------------------------
extern "C" void kernel_launch(void* const* d_in, const int* in_sizes, int n_in,
                              void* d_out, int out_size) {
    (void)in_sizes; (void)n_in; (void)out_size;
    const float* x     = (const float*)d_in[0];
    const float* scale = (const float*)d_in[1];
    const float* bias  = (const float*)d_in[2];
    const float* w1    = (const float*)d_in[3];  // [H, 2, I] row-major == [H, 2*I]
    const float* w2    = (const float*)d_in[4];  // [I, H]
    float* out = (float*)d_out;

    cudaFuncSetAttribute(mm_kernel<true, 128>, cudaFuncAttributeMaxDynamicSharedMemorySize, (int)GSMEM);
    cudaFuncSetAttribute(mm_kernel<false, 16>, cudaFuncAttributeMaxDynamicSharedMemorySize, (int)GSMEM);

    transpose_w1<<<dim3((2 * INTER) / 32, HID / 32), dim3(32, 8)>>>(w1);
    transpose_w2<<<dim3(HID / 32, INTER / 32), dim3(32, 8)>>>(w2);
    ln_kernel<<<M_TOK, 256>>>(x, scale, bias);

    // GEMM1 + fused GeGLU: [8192 x 2048] @ W1t^T -> g_z   (64 x 128 tiles)
    mm_kernel<true, 128><<<(M_TOK / CBM) * (2 * INTER / CBN), 256, GSMEM>>>(nullptr, HID);
    // GEMM2: [8192 x 8192] @ W2t^T -> out                  (64 x 16 tiles)
    mm_kernel<false, 16><<<(M_TOK / CBM) * (HID / CBN), 256, GSMEM>>>(out, INTER);
}